// round 11
// baseline (speedup 1.0000x reference)
#include <cuda_runtime.h>
#include <cuda_fp16.h>
#include <cuda_fp8.h>
#include <cstdint>

// ---------------------------------------------------------------------------
// LogMM: out = log(X @ M). Collapses to log(max(X@M, tiny)).
// sm_103 (no 'a') target: tcgen05/TMA unavailable -> fp8 mma.sync m16n8k32.
// R10: warp tile 32x32, CTA tile 64x128, full fragment double-buffering
// (regs ~90 < 128 cap), 2048 CTAs -> 1.2% wave quantization.
// ---------------------------------------------------------------------------

#define M_TOTAL 16384
#define N_TOTAL 1024
#define K_TOTAL 1024
#define TM 64
#define TN 128
#define KC 128                      // k per chunk (128 fp8 = 128B rows)
#define NCHUNK (K_TOTAL / KC)       // 8
#define STAGES 3
#define ROWB 144                    // 128B payload + 16B pad
#define A_BYTES (TM * ROWB)         // 9216
#define B_BYTES (TN * ROWB)         // 18432
#define STG (A_BYTES + B_BYTES)     // 27648
#define SMEM_TOTAL (STAGES * STG)   // 82944 -> 2 CTAs/SM (166 KB)

// Scratch (static device globals — no runtime allocation)
__device__ __align__(1024) uint8_t g_A8[(size_t)M_TOTAL * K_TOTAL];   // 16 MB fp8 X
__device__ __align__(1024) uint8_t g_B8[(size_t)N_TOTAL * K_TOTAL];   // 1 MB fp8 M^T

// ---------------------------------------------------------------------------
static __device__ __forceinline__ uint32_t smem_u32(const void* p) {
    uint32_t r;
    asm("{ .reg .u64 t; cvta.to.shared.u64 t, %1; cvt.u32.u64 %0, t; }"
        : "=r"(r) : "l"(p));
    return r;
}

#define CP_ASYNC16(dst, src) \
    asm volatile("cp.async.cg.shared.global [%0], [%1], 16;" :: "r"(dst), "l"(src) : "memory")
#define CP_COMMIT() asm volatile("cp.async.commit_group;" ::: "memory")
#define CP_WAIT(n)  asm volatile("cp.async.wait_group %0;" :: "n"(n) : "memory")

#define LDSM_X4(r0, r1, r2, r3, addr) \
    asm volatile("ldmatrix.sync.aligned.m8n8.x4.shared.b16 {%0,%1,%2,%3}, [%4];" \
                 : "=r"(r0), "=r"(r1), "=r"(r2), "=r"(r3) : "r"(addr))

// FP8 e4m3 MMA, f32 accumulate: D[16x8] += A[16x32] * B[32x8]
#define MMA16832(d, a0, a1, a2, a3, b0, b1) \
    asm volatile("mma.sync.aligned.m16n8k32.row.col.f32.e4m3.e4m3.f32 " \
                 "{%0,%1,%2,%3}, {%4,%5,%6,%7}, {%8,%9}, {%0,%1,%2,%3};" \
                 : "+f"((d)[0]), "+f"((d)[1]), "+f"((d)[2]), "+f"((d)[3]) \
                 : "r"(a0), "r"(a1), "r"(a2), "r"(a3), "r"(b0), "r"(b1))

// Pack 4 floats -> 4 e4m3 bytes (same routine for A and B: any within-pair
// byte order is a consistent k-permutation -> GEMM-invariant).
static __device__ __forceinline__ uint32_t pack_fp8x4(float a, float b, float c, float d) {
    __nv_fp8x2_storage_t lo =
        __nv_cvt_float2_to_fp8x2(make_float2(a, b), __NV_SATFINITE, __NV_E4M3);
    __nv_fp8x2_storage_t hi =
        __nv_cvt_float2_to_fp8x2(make_float2(c, d), __NV_SATFINITE, __NV_E4M3);
    return (uint32_t)lo | ((uint32_t)hi << 16);
}

// ---------------------------------------------------------------------------
// Fused conversion. Blocks [0,4096): X f32 -> e4m3. Blocks [4096,5120):
// transpose+convert M.
// ---------------------------------------------------------------------------
__global__ void cvt_all_kernel(const float4* __restrict__ x, uint4* __restrict__ oA,
                               const float* __restrict__ m, uint32_t* __restrict__ btq) {
    if (blockIdx.x < 4096) {
        int i = blockIdx.x * 256 + threadIdx.x;   // 1M threads, 16 floats each
        float4 v0 = x[4 * i + 0];
        float4 v1 = x[4 * i + 1];
        float4 v2 = x[4 * i + 2];
        float4 v3 = x[4 * i + 3];
        uint4 w;
        w.x = pack_fp8x4(v0.x, v0.y, v0.z, v0.w);
        w.y = pack_fp8x4(v1.x, v1.y, v1.z, v1.w);
        w.z = pack_fp8x4(v2.x, v2.y, v2.z, v2.w);
        w.w = pack_fp8x4(v3.x, v3.y, v3.z, v3.w);
        oA[i] = w;
    } else {
        __shared__ float tile[32][33];
        int b = blockIdx.x - 4096;
        int bx = b & 31;   // n-block
        int by = b >> 5;   // k-block
        int t = threadIdx.x;
        int tx = t & 31;
        int ty = t >> 5;
#pragma unroll
        for (int r = 0; r < 4; r++)  // tile[k_local][n_local]
            tile[ty + r * 8][tx] = m[(size_t)(by * 32 + ty + r * 8) * 1024 + bx * 32 + tx];
        __syncthreads();
        int n_local = t >> 3;   // 0..31
        int kq = t & 7;         // k quad
        float e0 = tile[kq * 4 + 0][n_local];
        float e1 = tile[kq * 4 + 1][n_local];
        float e2 = tile[kq * 4 + 2][n_local];
        float e3 = tile[kq * 4 + 3][n_local];
        btq[((size_t)(bx * 32 + n_local) * 1024 + by * 32 + kq * 4) >> 2] =
            pack_fp8x4(e0, e1, e2, e3);
    }
}

// ---------------------------------------------------------------------------
// GEMM + log epilogue. 2048 CTAs: ntile = bid & 7 (A-panel L2 reuse),
// mtile = bid >> 3 (0..255). 256 threads = 8 warps in 2(m) x 4(n);
// warp tile 32x32. Per k32 step: 4 LDSM.x4 + 8 MMA, fragments double-buffered.
// ---------------------------------------------------------------------------
__global__ void __launch_bounds__(256, 2)
gemm_log_kernel(float* __restrict__ out) {
    extern __shared__ char smem[];
    const uint32_t sb = smem_u32(smem);

    const int tid = threadIdx.x;
    const int lane = tid & 31;
    const int wid = tid >> 5;
    const int wm = wid >> 2;     // 0..1
    const int wn = wid & 3;      // 0..3
    const int mtile = blockIdx.x >> 3;
    const int ntile = blockIdx.x & 7;

    const uint8_t* gA = g_A8 + (size_t)(mtile * TM) * K_TOTAL;
    const uint8_t* gB = g_B8 + (size_t)(ntile * TN) * K_TOTAL;

    // loader: 256 threads, 6 x 16B each per stage (2 A rows + 4 B rows)
    const int lrow0 = tid >> 3;  // 0..31
    const int lseg = tid & 7;    // 0..7

    float acc[2][4][4];
#pragma unroll
    for (int i = 0; i < 2; i++)
#pragma unroll
        for (int j = 0; j < 4; j++)
#pragma unroll
            for (int c = 0; c < 4; c++) acc[i][j][c] = 0.0f;

    // ---- prologue: fill STAGES-1 stages ----
#pragma unroll
    for (int s = 0; s < STAGES - 1; s++) {
        const uint32_t sA = sb + s * STG;
        const uint32_t sB = sA + A_BYTES;
#pragma unroll
        for (int i = 0; i < 2; i++) {
            int row = lrow0 + i * 32;
            CP_ASYNC16(sA + row * ROWB + lseg * 16,
                       gA + (size_t)row * K_TOTAL + s * KC + lseg * 16);
        }
#pragma unroll
        for (int i = 0; i < 4; i++) {
            int row = lrow0 + i * 32;
            CP_ASYNC16(sB + row * ROWB + lseg * 16,
                       gB + (size_t)row * K_TOTAL + s * KC + lseg * 16);
        }
        CP_COMMIT();
    }

    const int lr = lane & 15;
    const int lk = (lane & 16) ? 16 : 0;

    for (int c = 0; c < NCHUNK; c++) {
        CP_WAIT(STAGES - 2);
        __syncthreads();

        if (c + STAGES - 1 < NCHUNK) {
            const int ck = c + STAGES - 1;
            const uint32_t sA = sb + (ck % STAGES) * STG;
            const uint32_t sB = sA + A_BYTES;
#pragma unroll
            for (int i = 0; i < 2; i++) {
                int row = lrow0 + i * 32;
                CP_ASYNC16(sA + row * ROWB + lseg * 16,
                           gA + (size_t)row * K_TOTAL + ck * KC + lseg * 16);
            }
#pragma unroll
            for (int i = 0; i < 4; i++) {
                int row = lrow0 + i * 32;
                CP_ASYNC16(sB + row * ROWB + lseg * 16,
                           gB + (size_t)row * K_TOTAL + ck * KC + lseg * 16);
            }
        }
        CP_COMMIT();

        // ---- compute chunk c: 4 k32 steps, double-buffered fragments ----
        const uint32_t stg = sb + (c % STAGES) * STG;
        const uint32_t sA = stg + (wm * 32 + lr) * ROWB + lk;
        const uint32_t sB = stg + A_BYTES + (wn * 32 + lr) * ROWB + lk;

        uint32_t a[2][2][4], b[2][2][4];
        // preload step 0
#pragma unroll
        for (int mi = 0; mi < 2; mi++)
            LDSM_X4(a[0][mi][0], a[0][mi][1], a[0][mi][2], a[0][mi][3],
                    sA + mi * 16 * ROWB);
#pragma unroll
        for (int bi = 0; bi < 2; bi++)
            LDSM_X4(b[0][bi][0], b[0][bi][1], b[0][bi][2], b[0][bi][3],
                    sB + bi * 16 * ROWB);

#pragma unroll
        for (int ks = 0; ks < KC / 32; ks++) {
            const int cur = ks & 1, nxt = cur ^ 1;
            if (ks < KC / 32 - 1) {  // prefetch next step while MMAs drain
#pragma unroll
                for (int mi = 0; mi < 2; mi++)
                    LDSM_X4(a[nxt][mi][0], a[nxt][mi][1], a[nxt][mi][2], a[nxt][mi][3],
                            sA + mi * 16 * ROWB + (ks + 1) * 32);
#pragma unroll
                for (int bi = 0; bi < 2; bi++)
                    LDSM_X4(b[nxt][bi][0], b[nxt][bi][1], b[nxt][bi][2], b[nxt][bi][3],
                            sB + bi * 16 * ROWB + (ks + 1) * 32);
            }
#pragma unroll
            for (int mi = 0; mi < 2; mi++)
#pragma unroll
                for (int ni = 0; ni < 4; ni++) {
                    const int bi = ni >> 1, sel = ni & 1;
                    MMA16832(acc[mi][ni],
                             a[cur][mi][0], a[cur][mi][1], a[cur][mi][2], a[cur][mi][3],
                             b[cur][bi][sel], b[cur][bi][sel + 2]);
                }
        }
    }

    // ---- epilogue: log + store ----
    const int mbase = mtile * TM + wm * 32;
    const int nbase = ntile * TN + wn * 32;
    const float tiny = 1.17549435e-38f;
#pragma unroll
    for (int mi = 0; mi < 2; mi++) {
#pragma unroll
        for (int ni = 0; ni < 4; ni++) {
            const int r0 = mbase + mi * 16 + (lane >> 2);
            const int col = nbase + ni * 8 + (lane & 3) * 2;
            float2 v0, v1;
            v0.x = __logf(fmaxf(acc[mi][ni][0], tiny));
            v0.y = __logf(fmaxf(acc[mi][ni][1], tiny));
            v1.x = __logf(fmaxf(acc[mi][ni][2], tiny));
            v1.y = __logf(fmaxf(acc[mi][ni][3], tiny));
            *reinterpret_cast<float2*>(out + (size_t)r0 * N_TOTAL + col) = v0;
            *reinterpret_cast<float2*>(out + (size_t)(r0 + 8) * N_TOTAL + col) = v1;
        }
    }
}

// ---------------------------------------------------------------------------
extern "C" void kernel_launch(void* const* d_in, const int* in_sizes, int n_in,
                              void* d_out, int out_size) {
    const float* x = (const float*)d_in[0];    // [8,2048,1024] f32
    const float* mat = (const float*)d_in[1];  // [1024,1024] f32
    float* out = (float*)d_out;                // [8,2048,1024] f32

    void *pA = nullptr, *pB = nullptr;
    cudaGetSymbolAddress(&pA, g_A8);
    cudaGetSymbolAddress(&pB, g_B8);

    cudaFuncSetAttribute(gemm_log_kernel, cudaFuncAttributeMaxDynamicSharedMemorySize,
                         SMEM_TOTAL);

    // 1) fused conversion: X -> e4m3, M -> transposed e4m3
    cvt_all_kernel<<<5120, 256>>>((const float4*)x, (uint4*)pA, mat, (uint32_t*)pB);
    // 2) GEMM + log epilogue: 256 m-tiles x 8 n-tiles
    gemm_log_kernel<<<2048, 256, SMEM_TOTAL>>>(out);
}

// round 15
// speedup vs baseline: 1.0850x; 1.0850x over previous
#include <cuda_runtime.h>
#include <cuda_fp16.h>
#include <cuda_fp8.h>
#include <cstdint>

// ---------------------------------------------------------------------------
// LogMM: out = log(X @ M). Collapses to log(max(X@M, tiny)).
// sm_103 (no 'a') target: tcgen05/TMA unavailable -> fp8 mma.sync m16n8k32.
// R12: back to 64x64 warp tile (best measured: operand-reuse-bound problem),
// restructured register-lean inner loop to eliminate R8's spills:
//  - B fragments resident per k-step, A fragments streamed (one LDSM -> 8 MMA)
//  - hoisted pointer arithmetic (one u64 base per tensor, += KC per chunk)
// ---------------------------------------------------------------------------

#define M_TOTAL 16384
#define N_TOTAL 1024
#define K_TOTAL 1024
#define TM 128
#define TN 128
#define KC 128                      // k per chunk (128 fp8 = 128B rows)
#define NCHUNK (K_TOTAL / KC)       // 8
#define STAGES 3
#define ROWB 144                    // 128B payload + 16B pad
#define A_BYTES (TM * ROWB)         // 18432
#define STG (2 * A_BYTES)           // 36864
#define SMEM_TOTAL (STAGES * STG)   // 110592 -> 2 CTAs/SM (221 KB)

// Scratch (static device globals — no runtime allocation)
__device__ __align__(1024) uint8_t g_A8[(size_t)M_TOTAL * K_TOTAL];   // 16 MB fp8 X
__device__ __align__(1024) uint8_t g_B8[(size_t)N_TOTAL * K_TOTAL];   // 1 MB fp8 M^T

// ---------------------------------------------------------------------------
static __device__ __forceinline__ uint32_t smem_u32(const void* p) {
    uint32_t r;
    asm("{ .reg .u64 t; cvta.to.shared.u64 t, %1; cvt.u32.u64 %0, t; }"
        : "=r"(r) : "l"(p));
    return r;
}

#define CP_ASYNC16(dst, src) \
    asm volatile("cp.async.cg.shared.global [%0], [%1], 16;" :: "r"(dst), "l"(src) : "memory")
#define CP_COMMIT() asm volatile("cp.async.commit_group;" ::: "memory")
#define CP_WAIT(n)  asm volatile("cp.async.wait_group %0;" :: "n"(n) : "memory")

#define LDSM_X4(r0, r1, r2, r3, addr) \
    asm volatile("ldmatrix.sync.aligned.m8n8.x4.shared.b16 {%0,%1,%2,%3}, [%4];" \
                 : "=r"(r0), "=r"(r1), "=r"(r2), "=r"(r3) : "r"(addr))

// FP8 e4m3 MMA, f32 accumulate: D[16x8] += A[16x32] * B[32x8]
#define MMA16832(d, a0, a1, a2, a3, b0, b1) \
    asm volatile("mma.sync.aligned.m16n8k32.row.col.f32.e4m3.e4m3.f32 " \
                 "{%0,%1,%2,%3}, {%4,%5,%6,%7}, {%8,%9}, {%0,%1,%2,%3};" \
                 : "+f"((d)[0]), "+f"((d)[1]), "+f"((d)[2]), "+f"((d)[3]) \
                 : "r"(a0), "r"(a1), "r"(a2), "r"(a3), "r"(b0), "r"(b1))

// Pack 4 floats -> 4 e4m3 bytes (same routine for A and B: any within-pair
// byte order is a consistent k-permutation -> GEMM-invariant).
static __device__ __forceinline__ uint32_t pack_fp8x4(float a, float b, float c, float d) {
    __nv_fp8x2_storage_t lo =
        __nv_cvt_float2_to_fp8x2(make_float2(a, b), __NV_SATFINITE, __NV_E4M3);
    __nv_fp8x2_storage_t hi =
        __nv_cvt_float2_to_fp8x2(make_float2(c, d), __NV_SATFINITE, __NV_E4M3);
    return (uint32_t)lo | ((uint32_t)hi << 16);
}

// ---------------------------------------------------------------------------
// Fused conversion. Blocks [0,4096): X f32 -> e4m3. Blocks [4096,5120):
// transpose+convert M.
// ---------------------------------------------------------------------------
__global__ void cvt_all_kernel(const float4* __restrict__ x, uint4* __restrict__ oA,
                               const float* __restrict__ m, uint32_t* __restrict__ btq) {
    if (blockIdx.x < 4096) {
        int i = blockIdx.x * 256 + threadIdx.x;   // 1M threads, 16 floats each
        float4 v0 = x[4 * i + 0];
        float4 v1 = x[4 * i + 1];
        float4 v2 = x[4 * i + 2];
        float4 v3 = x[4 * i + 3];
        uint4 w;
        w.x = pack_fp8x4(v0.x, v0.y, v0.z, v0.w);
        w.y = pack_fp8x4(v1.x, v1.y, v1.z, v1.w);
        w.z = pack_fp8x4(v2.x, v2.y, v2.z, v2.w);
        w.w = pack_fp8x4(v3.x, v3.y, v3.z, v3.w);
        oA[i] = w;
    } else {
        __shared__ float tile[32][33];
        int b = blockIdx.x - 4096;
        int bx = b & 31;   // n-block
        int by = b >> 5;   // k-block
        int t = threadIdx.x;
        int tx = t & 31;
        int ty = t >> 5;
#pragma unroll
        for (int r = 0; r < 4; r++)  // tile[k_local][n_local]
            tile[ty + r * 8][tx] = m[(size_t)(by * 32 + ty + r * 8) * 1024 + bx * 32 + tx];
        __syncthreads();
        int n_local = t >> 3;   // 0..31
        int kq = t & 7;         // k quad
        float e0 = tile[kq * 4 + 0][n_local];
        float e1 = tile[kq * 4 + 1][n_local];
        float e2 = tile[kq * 4 + 2][n_local];
        float e3 = tile[kq * 4 + 3][n_local];
        btq[((size_t)(bx * 32 + n_local) * 1024 + by * 32 + kq * 4) >> 2] =
            pack_fp8x4(e0, e1, e2, e3);
    }
}

// ---------------------------------------------------------------------------
// GEMM + log epilogue. 1024 CTAs: ntile = bid & 7 (A-panel L2 reuse),
// mtile = bid >> 3. 128 threads = 4 warps in 2x2; warp tile 64x64.
// Per k32 step: 4 B-LDSM resident, then stream A: (1 LDSM -> 8 MMA) x 4.
// ---------------------------------------------------------------------------
__global__ void __launch_bounds__(128, 2)
gemm_log_kernel(float* __restrict__ out) {
    extern __shared__ char smem[];
    const uint32_t sb = smem_u32(smem);

    const int tid = threadIdx.x;
    const int lane = tid & 31;
    const int wid = tid >> 5;
    const int wm = wid >> 1;     // 0..1
    const int wn = wid & 1;      // 0..1
    const int mtile = blockIdx.x >> 3;
    const int ntile = blockIdx.x & 7;

    // --- hoisted loader addressing: one u64 base each, += KC per chunk ---
    const int lrow0 = tid >> 3;  // 0..15
    const int lseg = tid & 7;    // 0..7
    const uint8_t* pa = g_A8 + (size_t)(mtile * TM + lrow0) * K_TOTAL + lseg * 16;
    const uint8_t* pb = g_B8 + (size_t)(ntile * TN + lrow0) * K_TOTAL + lseg * 16;
    const uint32_t dA0 = sb + lrow0 * ROWB + lseg * 16;           // + stage*STG
    const uint32_t dB0 = dA0 + A_BYTES;

    float acc[4][8][4];
#pragma unroll
    for (int i = 0; i < 4; i++)
#pragma unroll
        for (int j = 0; j < 8; j++)
#pragma unroll
            for (int c = 0; c < 4; c++) acc[i][j][c] = 0.0f;

    // ---- prologue: fill stages 0,1 ----
#pragma unroll
    for (int s = 0; s < STAGES - 1; s++) {
#pragma unroll
        for (int i = 0; i < 8; i++) {
            CP_ASYNC16(dA0 + s * STG + i * (16 * ROWB), pa + i * (16 * K_TOTAL));
            CP_ASYNC16(dB0 + s * STG + i * (16 * ROWB), pb + i * (16 * K_TOTAL));
        }
        pa += KC;
        pb += KC;
        CP_COMMIT();
    }

    // --- compute-side smem bases (rotate by stage) ---
    const int lr = lane & 15;
    const int lk = (lane & 16) ? 16 : 0;
    const uint32_t rA0 = sb + (wm * 64 + lr) * ROWB + lk;
    const uint32_t rB0 = sb + A_BYTES + (wn * 64 + lr) * ROWB + lk;

    int ld_stage = STAGES - 1;   // stage to fill next
    int cp_stage = 0;            // stage to compute from

    for (int c = 0; c < NCHUNK; c++) {
        CP_WAIT(STAGES - 2);
        __syncthreads();

        if (c + STAGES - 1 < NCHUNK) {
            const uint32_t dA = dA0 + ld_stage * STG;
            const uint32_t dB = dB0 + ld_stage * STG;
#pragma unroll
            for (int i = 0; i < 8; i++) {
                CP_ASYNC16(dA + i * (16 * ROWB), pa + i * (16 * K_TOTAL));
                CP_ASYNC16(dB + i * (16 * ROWB), pb + i * (16 * K_TOTAL));
            }
            pa += KC;
            pb += KC;
            if (++ld_stage == STAGES) ld_stage = 0;
        }
        CP_COMMIT();

        // ---- compute chunk c: 4 k32 steps ----
        const uint32_t sA = rA0 + cp_stage * STG;
        const uint32_t sB = rB0 + cp_stage * STG;
        if (++cp_stage == STAGES) cp_stage = 0;

#pragma unroll
        for (int ks = 0; ks < KC / 32; ks++) {
            uint32_t b[4][4];
#pragma unroll
            for (int bi = 0; bi < 4; bi++)
                LDSM_X4(b[bi][0], b[bi][1], b[bi][2], b[bi][3],
                        sB + bi * 16 * ROWB + ks * 32);
#pragma unroll
            for (int mi = 0; mi < 4; mi++) {
                uint32_t a0, a1, a2, a3;
                LDSM_X4(a0, a1, a2, a3, sA + mi * 16 * ROWB + ks * 32);
#pragma unroll
                for (int ni = 0; ni < 8; ni++) {
                    const int bi = ni >> 1, sel = ni & 1;
                    MMA16832(acc[mi][ni], a0, a1, a2, a3, b[bi][sel], b[bi][sel + 2]);
                }
            }
        }
    }

    // ---- epilogue: log + store ----
    const int mbase = mtile * TM + wm * 64;
    const int nbase = ntile * TN + wn * 64;
    const float tiny = 1.17549435e-38f;
#pragma unroll
    for (int mi = 0; mi < 4; mi++) {
#pragma unroll
        for (int ni = 0; ni < 8; ni++) {
            const int r0 = mbase + mi * 16 + (lane >> 2);
            const int col = nbase + ni * 8 + (lane & 3) * 2;
            float2 v0, v1;
            v0.x = __logf(fmaxf(acc[mi][ni][0], tiny));
            v0.y = __logf(fmaxf(acc[mi][ni][1], tiny));
            v1.x = __logf(fmaxf(acc[mi][ni][2], tiny));
            v1.y = __logf(fmaxf(acc[mi][ni][3], tiny));
            *reinterpret_cast<float2*>(out + (size_t)r0 * N_TOTAL + col) = v0;
            *reinterpret_cast<float2*>(out + (size_t)(r0 + 8) * N_TOTAL + col) = v1;
        }
    }
}

// ---------------------------------------------------------------------------
extern "C" void kernel_launch(void* const* d_in, const int* in_sizes, int n_in,
                              void* d_out, int out_size) {
    const float* x = (const float*)d_in[0];    // [8,2048,1024] f32
    const float* mat = (const float*)d_in[1];  // [1024,1024] f32
    float* out = (float*)d_out;                // [8,2048,1024] f32

    void *pA = nullptr, *pB = nullptr;
    cudaGetSymbolAddress(&pA, g_A8);
    cudaGetSymbolAddress(&pB, g_B8);

    cudaFuncSetAttribute(gemm_log_kernel, cudaFuncAttributeMaxDynamicSharedMemorySize,
                         SMEM_TOTAL);

    // 1) fused conversion: X -> e4m3, M -> transposed e4m3
    cvt_all_kernel<<<5120, 256>>>((const float4*)x, (uint4*)pA, mat, (uint32_t*)pB);
    // 2) GEMM + log epilogue: 128 m-tiles x 8 n-tiles
    gemm_log_kernel<<<1024, 128, SMEM_TOTAL>>>(out);
}